// round 4
// baseline (speedup 1.0000x reference)
#include <cuda_runtime.h>

#define FEAT 128
#define HID  32
#define NCOL 64          // 32 z + 32 h fused columns
#define TPB  256
#define NPB  256         // nodes per block
#define KT   16          // k-values per tile
#define NKT  (FEAT / KT) // 8 tiles

// Interleaved fused weights: row k, quarter q (0..3) holds
//   [z_{8q}..z_{8q+7}, h_{8q}..h_{8q+7}]  (16 floats per quarter)
__device__ __align__(16) float g_W[FEAT * NCOL];

// W tensors shape (2,1,160,32); [s,0,k,j] = s*5120 + k*32 + j. Only k<128 live (H0=0).
__global__ void prep_kernel(const float* __restrict__ Wz, const float* __restrict__ Wh) {
    int idx = blockIdx.x * blockDim.x + threadIdx.x;   // 0..8191
    if (idx >= FEAT * NCOL) return;
    int k = idx >> 6;
    int j = idx & 63;
    int q = j >> 4;
    int c = j & 15;
    int jj = q * 8 + (c & 7);
    const float* W = (c < 8) ? Wz : Wh;
    g_W[idx] = W[k * HID + jj] + W[5120 + k * HID + jj];
}

__device__ __forceinline__ unsigned long long pack2(float v) {
    unsigned long long r;
    asm("mov.b64 %0, {%1, %1};" : "=l"(r) : "f"(v));
    return r;
}
__device__ __forceinline__ void fma2(unsigned long long& acc, unsigned long long a,
                                     unsigned long long b) {
    asm("fma.rn.f32x2 %0, %1, %2, %0;" : "+l"(acc) : "l"(a), "l"(b));
}
__device__ __forceinline__ void unpack2(unsigned long long v, float& lo, float& hi) {
    asm("mov.b64 {%0, %1}, %2;" : "=f"(lo), "=f"(hi) : "l"(v));
}
__device__ __forceinline__ float sigmoid_f(float v) {
    return __fdividef(1.0f, 1.0f + __expf(-v));
}
__device__ __forceinline__ float tanh_f(float v) {
    return 1.0f - __fdividef(2.0f, __expf(2.0f * v) + 1.0f);
}

__global__ void __launch_bounds__(TPB, 2)
dcrnn_kernel(const float* __restrict__ x,
             const float* __restrict__ bz, const float* __restrict__ bh,
             const float* __restrict__ wlin, const float* __restrict__ blin,
             float* __restrict__ out, int nNodes)
{
    __shared__ __align__(16) float sW[FEAT * NCOL];   // 32 KB, weights only

    {   // cooperative weight stage (L2-resident after first wave)
        const float4* src = (const float4*)g_W;
        float4*       dst = (float4*)sW;
        #pragma unroll
        for (int i = 0; i < (FEAT * NCOL / 4) / TPB; i++)   // 8
            dst[threadIdx.x + i * TPB] = src[threadIdx.x + i * TPB];
    }
    __syncthreads();

    const int lane  = threadIdx.x & 31;
    const int jq    = lane & 3;          // column quarter owned by this lane
    const int gbase = lane & 28;         // first lane of this 4-lane node group

    // Staging role: this thread loads the x row of node (blockStart + threadIdx.x)
    int node_stage = blockIdx.x * NPB + threadIdx.x;
    int ns_clamped = node_stage < nNodes ? node_stage : (nNodes - 1);
    const float4* xr = (const float4*)(x + (size_t)ns_clamped * FEAT);

    // Compute role: lanes gbase..gbase+3 jointly own nodes node0..node0+3
    const int node0 = blockIdx.x * NPB + (threadIdx.x & ~3);

    // acc[n][p]: packed f32x2 for thread-local columns (2p, 2p+1) of node n
    unsigned long long accz[4][4], acch[4][4];
    #pragma unroll
    for (int n = 0; n < 4; n++)
        #pragma unroll
        for (int p = 0; p < 4; p++) { accz[n][p] = 0ull; acch[n][p] = 0ull; }

    const float* wbase = sW + jq * 16;

    // Double-buffered x tile: prefetch kt+1 while computing kt
    float xs[KT], xn[KT];
    #pragma unroll
    for (int i = 0; i < 4; i++)
        *(float4*)(xs + 4 * i) = xr[i];                 // tile 0

    #pragma unroll 1
    for (int kt = 0; kt < NKT; kt++) {
        if (kt + 1 < NKT) {
            #pragma unroll
            for (int i = 0; i < 4; i++)
                *(float4*)(xn + 4 * i) = xr[(kt + 1) * 4 + i];  // prefetch next tile
        }

        #pragma unroll
        for (int s = 0; s < KT; s++) {
            const int k = kt * KT + s;
            const ulonglong2* wr = (const ulonglong2*)(wbase + k * NCOL);
            ulonglong2 wz0 = wr[0];   // z cols 0..3 (local)
            ulonglong2 wz1 = wr[1];   // z cols 4..7
            ulonglong2 wh0 = wr[2];   // h cols 0..3
            ulonglong2 wh1 = wr[3];   // h cols 4..7
            #pragma unroll
            for (int n = 0; n < 4; n++) {
                // broadcast x[node0+n][k] from its staging lane (same warp)
                float xk = __shfl_sync(0xffffffffu, xs[s], gbase + n);
                unsigned long long xx = pack2(xk);
                fma2(accz[n][0], xx, wz0.x);
                fma2(accz[n][1], xx, wz0.y);
                fma2(accz[n][2], xx, wz1.x);
                fma2(accz[n][3], xx, wz1.y);
                fma2(acch[n][0], xx, wh0.x);
                fma2(acch[n][1], xx, wh0.y);
                fma2(acch[n][2], xx, wh1.x);
                fma2(acch[n][3], xx, wh1.y);
            }
        }

        #pragma unroll
        for (int i = 0; i < KT; i++) xs[i] = xn[i];     // rotate buffers
    }

    // Epilogue: 8 local gate columns -> partial dot with W_lin, reduce over quarters
    float bzv[8], bhv[8], wlv[8];
    #pragma unroll
    for (int c = 0; c < 8; c++) {
        bzv[c] = __ldg(bz   + jq * 8 + c);
        bhv[c] = __ldg(bh   + jq * 8 + c);
        wlv[c] = __ldg(wlin + jq * 8 + c);
    }
    float blv = __ldg(blin);

    float res4[4];
    #pragma unroll
    for (int n = 0; n < 4; n++) {
        float partial = 0.0f;
        #pragma unroll
        for (int p = 0; p < 4; p++) {
            float z0, z1, h0, h1;
            unpack2(accz[n][p], z0, z1);
            unpack2(acch[n][p], h0, h1);
            int c0 = 2 * p, c1 = 2 * p + 1;
            {
                float z  = sigmoid_f(z0 + bzv[c0]);
                float ht = tanh_f(h0 + bhv[c0]);
                partial = fmaf(fmaxf((1.0f - z) * ht, 0.0f), wlv[c0], partial);
            }
            {
                float z  = sigmoid_f(z1 + bzv[c1]);
                float ht = tanh_f(h1 + bhv[c1]);
                partial = fmaf(fmaxf((1.0f - z) * ht, 0.0f), wlv[c1], partial);
            }
        }
        partial += __shfl_xor_sync(0xffffffffu, partial, 1);
        partial += __shfl_xor_sync(0xffffffffu, partial, 2);
        res4[n] = partial + blv;
    }

    if (jq == 0) {
        if (node0 + 3 < nNodes) {
            *(float4*)(out + node0) = make_float4(res4[0], res4[1], res4[2], res4[3]);
        } else {
            #pragma unroll
            for (int n = 0; n < 4; n++)
                if (node0 + n < nNodes) out[node0 + n] = res4[n];
        }
    }
}

// Inputs (metadata order):
// 0:x[N*128] f32   1:edge_index (dead)   2:edge_weight (dead)
// 3:W_z[10240]     4:b_z[32]   5:W_r (dead)   6:b_r (dead)
// 7:W_h[10240]     8:b_h[32]   9:W_lin[32]   10:b_lin[1]
extern "C" void kernel_launch(void* const* d_in, const int* in_sizes, int n_in,
                              void* d_out, int out_size) {
    const float* x     = (const float*)d_in[0];
    const float* W_z   = (const float*)d_in[3];
    const float* b_z   = (const float*)d_in[4];
    const float* W_h   = (const float*)d_in[7];
    const float* b_h   = (const float*)d_in[8];
    const float* W_lin = (const float*)d_in[9];
    const float* b_lin = (const float*)d_in[10];
    float* out = (float*)d_out;

    int nNodes = out_size;

    prep_kernel<<<(FEAT * NCOL + TPB - 1) / TPB, TPB>>>(W_z, W_h);
    int blocks = (nNodes + NPB - 1) / NPB;
    dcrnn_kernel<<<blocks, TPB>>>(x, b_z, b_h, W_lin, b_lin, out, nNodes);
}

// round 8
// speedup vs baseline: 3.1149x; 3.1149x over previous
#include <cuda_runtime.h>
#include <cuda_bf16.h>
#include <cstdint>

#define HID     32
#define TILE_M  256
#define THREADS 256
#define BSTRIDE 136                  // padded bf16 per B row (272B): conflict-free ldmatrix
#define BHALF   (64 * BSTRIDE)       // elements per version (hi/lo)

// Fused W^T, split bf16: [hi: 64 rows x 136][lo: same], row n = output col, k contiguous.
__device__ __align__(16) __nv_bfloat16 g_B[2 * BHALF];

// W tensors shape (2,1,160,32); [s,0,k,j] = s*5120 + k*32 + j; only k<128 live (H0=0).
// B[n][k]: n<32 -> z gate col n, n>=32 -> h gate col n-32.
__global__ void prep_kernel(const float* __restrict__ Wz, const float* __restrict__ Wh) {
    int idx = blockIdx.x * blockDim.x + threadIdx.x;   // 0..8191
    if (idx >= 64 * 128) return;
    int n = idx >> 7;
    int k = idx & 127;
    int j = n & 31;
    const float* W = (n < 32) ? Wz : Wh;
    float v = W[k * 32 + j] + W[5120 + k * 32 + j];
    __nv_bfloat16 hi = __float2bfloat16_rn(v);
    float lo = v - __bfloat162float(hi);
    g_B[n * BSTRIDE + k]         = hi;
    g_B[BHALF + n * BSTRIDE + k] = __float2bfloat16_rn(lo);
}

// ---------------- helpers ----------------
__device__ __forceinline__ uint32_t smem_u32(const void* p) {
    uint32_t a;
    asm("{ .reg .u64 t; cvta.to.shared.u64 t, %1; cvt.u32.u64 %0, t; }" : "=r"(a) : "l"(p));
    return a;
}
__device__ __forceinline__ void mma_bf16(float* d, const uint32_t* a, const uint32_t* b) {
    asm volatile(
        "mma.sync.aligned.m16n8k16.row.col.f32.bf16.bf16.f32 "
        "{%0,%1,%2,%3}, {%4,%5,%6,%7}, {%8,%9}, {%0,%1,%2,%3};"
        : "+f"(d[0]), "+f"(d[1]), "+f"(d[2]), "+f"(d[3])
        : "r"(a[0]), "r"(a[1]), "r"(a[2]), "r"(a[3]), "r"(b[0]), "r"(b[1]));
}
__device__ __forceinline__ void ldm_x4(uint32_t* r, uint32_t addr) {
    asm volatile("ldmatrix.sync.aligned.m8n8.x4.shared.b16 {%0,%1,%2,%3}, [%4];"
        : "=r"(r[0]), "=r"(r[1]), "=r"(r[2]), "=r"(r[3]) : "r"(addr));
}
__device__ __forceinline__ uint32_t pack_bf2(float a, float b) {
    __nv_bfloat162 t = __floats2bfloat162_rn(a, b);    // .x = a (low), .y = b (high)
    return *(uint32_t*)&t;
}
__device__ __forceinline__ float sigmoid_f(float v) {
    return __fdividef(1.0f, 1.0f + __expf(-v));
}
__device__ __forceinline__ float tanh_f(float v) {
    return 1.0f - __fdividef(2.0f, __expf(2.0f * v) + 1.0f);
}

__global__ void __launch_bounds__(THREADS, 2)
dcrnn_mma_kernel(const float* __restrict__ x,
                 const float* __restrict__ bz, const float* __restrict__ bh,
                 const float* __restrict__ wlin, const float* __restrict__ blin,
                 float* __restrict__ out, int nNodes)
{
    __shared__ __align__(16) __nv_bfloat16 sB[2 * BHALF];   // 34816 B

    const int tid = threadIdx.x;

    // stage B (hi+lo) -> smem, 2176 uint4
    {
        const uint4* src = (const uint4*)g_B;
        uint4*       dst = (uint4*)sB;
        #pragma unroll
        for (int i = 0; i < 2176 / THREADS + 1; i++) {
            int e = tid + i * THREADS;
            if (e < 2176) dst[e] = src[e];
        }
    }
    __syncthreads();

    const int warp = tid >> 5;
    const int lane = tid & 31;
    const int g    = lane >> 2;        // 0..7
    const int c    = lane & 3;         // 0..3
    const int rowBase = blockIdx.x * TILE_M + warp * 32;

    // 4 x-row pointers (rows g, g+8, g+16, g+24), clamped for loads
    const float* rowp[4];
    #pragma unroll
    for (int r = 0; r < 4; r++) {
        int rr = rowBase + g + 8 * r;
        if (rr >= nNodes) rr = nNodes - 1;
        rowp[r] = x + (size_t)rr * 128 + 2 * c;
    }

    // B ldmatrix per-thread address component:
    // tgrp = lane>>3: 0:(n=trow,kb0) 1:(n=trow,kb1) 2:(n=8+trow,kb0) 3:(n=8+trow,kb1)
    const uint32_t sB0 = smem_u32(sB);
    const uint32_t tb  = (uint32_t)((((lane >> 4) << 3) + (lane & 7)) * (BSTRIDE * 2)
                                    + ((lane >> 3) & 1) * 16);
    const uint32_t bbase = sB0 + tb;

    float acc[2][8][4];
    #pragma unroll
    for (int mt = 0; mt < 2; mt++)
        #pragma unroll
        for (int nt = 0; nt < 8; nt++)
            #pragma unroll
            for (int e = 0; e < 4; e++) acc[mt][nt][e] = 0.0f;

    #pragma unroll 2
    for (int kt = 0; kt < 8; kt++) {
        // A fragments straight from gmem: 8x LDG.64 (f32 pairs), split to bf16 hi/lo
        float2 av[4][2];
        #pragma unroll
        for (int r = 0; r < 4; r++) {
            av[r][0] = *(const float2*)(rowp[r] + kt * 16);
            av[r][1] = *(const float2*)(rowp[r] + kt * 16 + 8);
        }
        uint32_t Ah[2][4], Al[2][4];
        #pragma unroll
        for (int mt = 0; mt < 2; mt++)
            #pragma unroll
            for (int kb = 0; kb < 2; kb++)
                #pragma unroll
                for (int rr = 0; rr < 2; rr++) {
                    float2 v = av[mt * 2 + rr][kb];
                    __nv_bfloat162 h2 = __floats2bfloat162_rn(v.x, v.y);
                    float lx = v.x - __bfloat162float(h2.x);
                    float ly = v.y - __bfloat162float(h2.y);
                    Ah[mt][kb * 2 + rr] = *(uint32_t*)&h2;
                    Al[mt][kb * 2 + rr] = pack_bf2(lx, ly);
                }

        // B hi fragments: 4x ldmatrix.x4 covering 8 n-tiles
        uint32_t B2[8][2];
        #pragma unroll
        for (int p = 0; p < 8; p += 2) {
            uint32_t r4[4];
            ldm_x4(r4, bbase + p * (8 * BSTRIDE * 2) + kt * 32);
            B2[p][0] = r4[0]; B2[p][1] = r4[1];
            B2[p + 1][0] = r4[2]; B2[p + 1][1] = r4[3];
        }
        #pragma unroll
        for (int mt = 0; mt < 2; mt++)
            #pragma unroll
            for (int nt = 0; nt < 8; nt++)
                mma_bf16(acc[mt][nt], Ah[mt], B2[nt]);     // xh * wh
        #pragma unroll
        for (int mt = 0; mt < 2; mt++)
            #pragma unroll
            for (int nt = 0; nt < 8; nt++)
                mma_bf16(acc[mt][nt], Al[mt], B2[nt]);     // xl * wh

        // B lo fragments (reuse regs)
        #pragma unroll
        for (int p = 0; p < 8; p += 2) {
            uint32_t r4[4];
            ldm_x4(r4, bbase + 2 * BHALF + p * (8 * BSTRIDE * 2) + kt * 32);
            B2[p][0] = r4[0]; B2[p][1] = r4[1];
            B2[p + 1][0] = r4[2]; B2[p + 1][1] = r4[3];
        }
        #pragma unroll
        for (int mt = 0; mt < 2; mt++)
            #pragma unroll
            for (int nt = 0; nt < 8; nt++)
                mma_bf16(acc[mt][nt], Ah[mt], B2[nt]);     // xh * wl
    }

    // ---- epilogue: z at col j (n-tiles 0..3), h at col j+32 (n-tiles 4..7),
    //      both owned by the same thread. Quad shfl-reduce, lane c==0 stores.
    float bl = __ldg(blin);
    #pragma unroll
    for (int r = 0; r < 4; r++) {
        int mt = r >> 1;
        int eb = (r & 1) * 2;          // c0/c1 = row g, c2/c3 = row g+8
        float partial = 0.0f;
        #pragma unroll
        for (int ntz = 0; ntz < 4; ntz++) {
            #pragma unroll
            for (int e = 0; e < 2; e++) {
                int j = ntz * 8 + 2 * c + e;
                float zv = acc[mt][ntz][eb + e]     + __ldg(bz + j);
                float hv = acc[mt][ntz + 4][eb + e] + __ldg(bh + j);
                float zz = sigmoid_f(zv);
                float ht = tanh_f(hv);
                partial = fmaf(fmaxf((1.0f - zz) * ht, 0.0f), __ldg(wlin + j), partial);
            }
        }
        partial += __shfl_xor_sync(0xffffffffu, partial, 1);
        partial += __shfl_xor_sync(0xffffffffu, partial, 2);
        if (c == 0) {
            int grow = rowBase + g + 8 * r;
            if (grow < nNodes) out[grow] = partial + bl;
        }
    }
}

// Inputs (metadata order):
// 0:x[N*128] f32   1:edge_index (dead)   2:edge_weight (dead)
// 3:W_z[10240]     4:b_z[32]   5:W_r (dead)   6:b_r (dead)
// 7:W_h[10240]     8:b_h[32]   9:W_lin[32]   10:b_lin[1]
extern "C" void kernel_launch(void* const* d_in, const int* in_sizes, int n_in,
                              void* d_out, int out_size) {
    const float* x     = (const float*)d_in[0];
    const float* W_z   = (const float*)d_in[3];
    const float* b_z   = (const float*)d_in[4];
    const float* W_h   = (const float*)d_in[7];
    const float* b_h   = (const float*)d_in[8];
    const float* W_lin = (const float*)d_in[9];
    const float* b_lin = (const float*)d_in[10];
    float* out = (float*)d_out;

    int nNodes = out_size;

    prep_kernel<<<(64 * 128 + 255) / 256, 256>>>(W_z, W_h);
    int blocks = (nNodes + TILE_M - 1) / TILE_M;
    dcrnn_mma_kernel<<<blocks, THREADS>>>(x, b_z, b_h, W_lin, b_lin, out, nNodes);
}